// round 14
// baseline (speedup 1.0000x reference)
#include <cuda_runtime.h>
#include <cuda_fp16.h>
#include <cstdint>

// Problem constants
#define CB   8
#define HW   4096          // 64*64
#define CIN  512

// Device scratch (fp16: same 11-bit significand as tf32)
static __device__ __half  g_bfh[(size_t)CB * 512 * HW];   // base_feat fp16 (32MB)
static __device__ __half  g_rpn1h[(size_t)CB * 384 * HW]; // conv3 out (24MB)
static __device__ __half2 g_feath2[(size_t)CB * 64 * HW]; // convf_rpn pair-interleaved (8MB)
static __device__ __half  g_wah[512 * 512];               // [w_f; w_2]
static __device__ __half  g_wth[9 * 384 * 128];           // w_c1 tap-major
static __device__ __half  g_whh[64 * 384];                // [w_cls; w_box; 0]

// ---------------------------------------------------------------------------
// helpers
// ---------------------------------------------------------------------------
__device__ __forceinline__ void mma16(float d[4], const unsigned a[4], const unsigned b[2]) {
    asm volatile(
        "mma.sync.aligned.m16n8k16.row.col.f32.f16.f16.f32 "
        "{%0,%1,%2,%3}, {%4,%5,%6,%7}, {%8,%9}, {%0,%1,%2,%3};\n"
        : "+f"(d[0]), "+f"(d[1]), "+f"(d[2]), "+f"(d[3])
        : "r"(a[0]), "r"(a[1]), "r"(a[2]), "r"(a[3]), "r"(b[0]), "r"(b[1]));
}

__device__ __forceinline__ unsigned sptr(const void* p) {
    return (unsigned)__cvta_generic_to_shared(p);
}
__device__ __forceinline__ void cp16(unsigned d, const void* s, bool ok) {
    asm volatile("cp.async.cg.shared.global [%0], [%1], 16, %2;\n"
                 :: "r"(d), "l"(s), "r"(ok ? 16 : 0));
}
__device__ __forceinline__ void cpcommit() { asm volatile("cp.async.commit_group;\n"); }
__device__ __forceinline__ void cpwait2()  { asm volatile("cp.async.wait_group 2;\n"); }
__device__ __forceinline__ void cpwait0()  { asm volatile("cp.async.wait_group 0;\n"); }

__device__ __forceinline__ void ldm4(unsigned addr, unsigned& r0, unsigned& r1,
                                     unsigned& r2, unsigned& r3) {
    asm volatile("ldmatrix.sync.aligned.m8n8.x4.shared.b16 {%0,%1,%2,%3}, [%4];"
                 : "=r"(r0), "=r"(r1), "=r"(r2), "=r"(r3) : "r"(addr));
}
__device__ __forceinline__ void ldm4t(unsigned addr, unsigned& r0, unsigned& r1,
                                      unsigned& r2, unsigned& r3) {
    asm volatile("ldmatrix.sync.aligned.m8n8.x4.trans.shared.b16 {%0,%1,%2,%3}, [%4];"
                 : "=r"(r0), "=r"(r1), "=r"(r2), "=r"(r3) : "r"(addr));
}

// ---------------------------------------------------------------------------
// Prep: base_feat -> fp16; weights -> fp16 (tap-major for w_c1; packed head).
// ---------------------------------------------------------------------------
#define PREP_N4 4194304             // (8*512*4096)/4, float4 granularity
#define PREP_N1 262144              // 512*512
#define PREP_N2 442368              // 9*384*128
#define PREP_N3 24576               // 64*384
#define PREP_TOT (PREP_N4 + PREP_N1 + PREP_N2 + PREP_N3)

__global__ void k_prep(const float* __restrict__ base_feat,
                       const float* __restrict__ w_f, const float* __restrict__ w_2,
                       const float* __restrict__ w_c1,
                       const float* __restrict__ w_cls, const float* __restrict__ w_box)
{
    int i = blockIdx.x * 256 + threadIdx.x;
    if (i < PREP_N4) {
        float4 v = ((const float4*)base_feat)[i];
        __half2* dst = (__half2*)(g_bfh + (size_t)i * 4);
        dst[0] = __floats2half2_rn(v.x, v.y);
        dst[1] = __floats2half2_rn(v.z, v.w);
        return;
    }
    i -= PREP_N4;
    if (i < PREP_N1) {
        int m = i >> 9;
        float v = (m < 128) ? w_f[i] : w_2[i - 65536];
        g_wah[i] = __float2half_rn(v);
        return;
    }
    i -= PREP_N1;
    if (i < PREP_N2) {
        int tap = i / 49152, rem = i % 49152;
        int m = rem >> 7, c = rem & 127;
        g_wth[i] = __float2half_rn(w_c1[(size_t)m * 1152 + c * 9 + tap]);
        return;
    }
    i -= PREP_N2;
    if (i < PREP_N3) {
        int r = i / 384, k = i - r * 384;
        float v;
        if (r < 18)      v = w_cls[i];
        else if (r < 54) v = w_box[(r - 18) * 384 + k];
        else             v = 0.f;
        g_whh[i] = __float2half_rn(v);
    }
}

// ---------------------------------------------------------------------------
// Kernel 1: fused 1x1 conv 512 -> 512, ReLU -> d_out feat region.
// fp16 m16n8k16 + ldmatrix. 4 warps of 64x64, 128 thr. 4-slot K16 ring,
// ONE wait_group(0)+__syncthreads per K32 stage-pair:
//   per u: [ldm(s1) | mma(s0) | mma(s1)] -> wait0+sync -> load s+4,s+5 -> ldm(s+2)
// mt==0 also writes PAIR-INTERLEAVED fp16 channels 0..127 to g_feath2.
// ---------------------------------------------------------------------------
#define C1_A_B  6144
#define C1_B_B  4352
#define C1_ST_B (C1_A_B + C1_B_B)   // 10496
#define C1_SMEM (4 * C1_ST_B)       // 41984

__global__ __launch_bounds__(128, 2)
void k_conv1(const float* __restrict__ b_f, const float* __restrict__ b_2,
             float* __restrict__ out)
{
    extern __shared__ char ds[];
    const int n  = blockIdx.z;
    const int mt = blockIdx.y;
    const int n0 = blockIdx.x * 128;
    const int mtb = mt * 128;
    const float* bi = (mt == 0) ? b_f : (b_2 + (mt - 1) * 128);
    const __half* Bp = g_bfh + (size_t)n * CIN * HW + n0;

    const int tid  = threadIdx.x;
    const int warp = tid >> 5, lane = tid & 31;
    const int wm = (warp >> 1) * 64, wn = (warp & 1) * 64;
    const int g  = lane >> 2, t4 = lane & 3;
    const int l15 = lane & 15, l16 = lane >> 4;

    auto loadT = [&](int s) {
        if (s < 32) {
            char* As = ds + (s & 3) * C1_ST_B;
            char* Bs = As + C1_A_B;
            const int k0 = s * 16;
            #pragma unroll
            for (int j = 0; j < 2; j++) {
                int e = tid + j * 128;
                int row = e >> 1, sub = e & 1;
                cp16(sptr(As + row * 48 + sub * 16),
                     g_wah + (size_t)(mtb + row) * 512 + k0 + sub * 8, true);
                int brow = e >> 4, xu = e & 15;
                cp16(sptr(Bs + brow * 272 + xu * 16),
                     Bp + (size_t)(k0 + brow) * HW + xu * 8, true);
            }
        }
        cpcommit();
    };

    auto ldmAB = [&](int s, unsigned (&a)[4][4], unsigned (&b)[8][2]) {
        const char* As = ds + (s & 3) * C1_ST_B;
        const char* Bs = As + C1_A_B;
        #pragma unroll
        for (int mf = 0; mf < 4; mf++) {
            unsigned addr = sptr(As) + (wm + mf * 16 + l15) * 48 + l16 * 16;
            ldm4(addr, a[mf][0], a[mf][1], a[mf][2], a[mf][3]);
        }
        #pragma unroll
        for (int p = 0; p < 4; p++) {
            unsigned addr = sptr(Bs) + l15 * 272 + (wn + p * 16 + l16 * 8) * 2;
            ldm4t(addr, b[2*p][0], b[2*p][1], b[2*p+1][0], b[2*p+1][1]);
        }
    };

    float acc[4][8][4] = {};
    unsigned aA[4][4], bA[8][2], aB[4][4], bB[8][2];

    loadT(0); loadT(1); loadT(2); loadT(3);
    cpwait2();                                  // stages 0,1 complete
    __syncthreads();
    ldmAB(0, aA, bA);

    for (int u = 0; u < 16; u++) {
        const int t0 = 2 * u;
        ldmAB(t0 + 1, aB, bB);
        #pragma unroll
        for (int mf = 0; mf < 4; mf++)
            #pragma unroll
            for (int nf = 0; nf < 8; nf++) mma16(acc[mf][nf], aA[mf], bA[nf]);
        #pragma unroll
        for (int mf = 0; mf < 4; mf++)
            #pragma unroll
            for (int nf = 0; nf < 8; nf++) mma16(acc[mf][nf], aB[mf], bB[nf]);
        if (u + 1 < 16) {
            cpwait0();                          // stages t0+2, t0+3 complete
            __syncthreads();                    // slots t0, t0+1 reusable
            loadT(t0 + 4); loadT(t0 + 5);
            ldmAB(t0 + 2, aA, bA);
        }
    }
    cpwait0();

    float*   outb = out + (size_t)n * CIN * HW + (size_t)mt * 128 * HW;
    __half2* gf2  = g_feath2 + (size_t)n * 64 * HW;
    #pragma unroll
    for (int mf = 0; mf < 4; mf++) {
        int r0 = wm + mf * 16 + g;
        float bv0 = bi[r0], bv1 = bi[r0 + 8];
        #pragma unroll
        for (int nf = 0; nf < 8; nf++) {
            int c = n0 + wn + nf * 8 + t4 * 2;
            float2 v0, v1;
            v0.x = fmaxf(acc[mf][nf][0] + bv0, 0.f);
            v0.y = fmaxf(acc[mf][nf][1] + bv0, 0.f);
            v1.x = fmaxf(acc[mf][nf][2] + bv1, 0.f);
            v1.y = fmaxf(acc[mf][nf][3] + bv1, 0.f);
            *(float2*)(outb + (size_t)r0 * HW + c)       = v0;
            *(float2*)(outb + (size_t)(r0 + 8) * HW + c) = v1;
            if (mt == 0) {
                // pair-interleave: partner lane+4 holds channel r0+1
                float p0x = __shfl_down_sync(0xffffffffu, v0.x, 4);
                float p0y = __shfl_down_sync(0xffffffffu, v0.y, 4);
                float p1x = __shfl_down_sync(0xffffffffu, v1.x, 4);
                float p1y = __shfl_down_sync(0xffffffffu, v1.y, 4);
                if (!(g & 1)) {
                    __half2* d0 = gf2 + (size_t)(r0 >> 1) * HW + c;
                    d0[0] = __floats2half2_rn(v0.x, p0x);
                    d0[1] = __floats2half2_rn(v0.y, p0y);
                    __half2* d1 = gf2 + (size_t)((r0 >> 1) + 4) * HW + c;
                    d1[0] = __floats2half2_rn(v1.x, p1x);
                    d1[1] = __floats2half2_rn(v1.y, p1y);
                }
            }
        }
    }
}

// ---------------------------------------------------------------------------
// Kernel 2: 3x3 conv 128 -> 384 pad=1, ReLU -> g_rpn1h (fp16).
// fp16 m16n8k16. A via ldmatrix from 4-slot ring; B = one aligned LDS.32 per
// register from PAIR-INTERLEAVED halo tiles. One wait0+sync per stage-pair.
// H(kc) bundled into stage-9kc commit; 2 H buffers at kc cadence.
// ---------------------------------------------------------------------------
#define H2_ROW   68
#define H2_PAD   4
#define H2_SLICE 280                // __half2 units
#define H2_BUF   (8 * H2_SLICE)     // 2240 __half2 per buffer
#define C3_A_B   6144
#define C3_SMEM  (4 * C3_A_B + 2 * H2_BUF * 4)   // 42496

__global__ __launch_bounds__(128, 2)
void k_conv3(const float* __restrict__ b_c1)
{
    extern __shared__ char ds[];
    __half2* Hb2 = (__half2*)(ds + 4 * C3_A_B);

    const int n  = blockIdx.z;
    const int m0 = blockIdx.y * 128;
    const int n0 = blockIdx.x * 128;
    const int y0 = blockIdx.x * 2;

    const int tid  = threadIdx.x;
    const int warp = tid >> 5, lane = tid & 31;
    const int wm = (warp >> 1) * 64, wn = (warp & 1) * 64;
    const int g  = lane >> 2, t4 = lane & 3;
    const int l15 = lane & 15, l16 = lane >> 4;

    // zero pads: per (buf,k2): front 4 __half2 + halo cols 64..67 of 4 rows
    for (int i = tid; i < 320; i += 128) {
        int buf = i / 160, r2 = i % 160;
        int k2 = r2 / 20, e = r2 % 20;
        int off = (e < 4) ? e
                          : H2_PAD + ((e - 4) >> 2) * H2_ROW + 64 + ((e - 4) & 3);
        Hb2[buf * H2_BUF + k2 * H2_SLICE + off] = __floats2half2_rn(0.f, 0.f);
    }

    auto loadH = [&](int kc, int buf) {
        const __half2* src = g_feath2 + (size_t)n * 64 * HW;
        #pragma unroll
        for (int j = 0; j < 4; j++) {
            int e = tid + j * 128;                 // 0..511
            int k2 = e >> 6, rem = e & 63, r = rem >> 4, xu = rem & 15;
            int gy = y0 - 1 + r;
            cp16(sptr(Hb2 + buf * H2_BUF + k2 * H2_SLICE + H2_PAD + r * H2_ROW + xu * 4),
                 src + (size_t)(kc * 8 + k2) * HW + gy * 64 + xu * 4,
                 (unsigned)gy < 64u);
        }
    };
    auto loadT = [&](int s) {
        if (s < 72) {
            int kc = s / 9, tap = s - kc * 9;
            char* As = ds + (s & 3) * C3_A_B;
            #pragma unroll
            for (int j = 0; j < 2; j++) {
                int e = tid + j * 128;
                int row = e >> 1, sub = e & 1;
                cp16(sptr(As + row * 48 + sub * 16),
                     g_wth + ((size_t)tap * 384 + m0 + row) * 128 + kc * 16 + sub * 8, true);
            }
            if (tap == 0 && kc < 8) loadH(kc, kc & 1);
        }
        cpcommit();
    };

    int ib2[8];
    #pragma unroll
    for (int nf = 0; nf < 8; nf++) {
        int px = wn + nf * 8 + g;
        ib2[nf] = H2_PAD + (1 + (px >> 6)) * H2_ROW + (px & 63);
    }

    auto ldfr = [&](int s, unsigned (&a)[4][4], unsigned (&b)[8][2]) {
        int kc = s / 9, tap = s - kc * 9;
        int hoff = (tap / 3 - 1) * H2_ROW + (tap % 3 - 1);
        const char* As = ds + (s & 3) * C3_A_B;
        const __half2* Hc = Hb2 + (kc & 1) * H2_BUF;
        #pragma unroll
        for (int mf = 0; mf < 4; mf++) {
            unsigned addr = sptr(As) + (wm + mf * 16 + l15) * 48 + l16 * 16;
            ldm4(addr, a[mf][0], a[mf][1], a[mf][2], a[mf][3]);
        }
        const __half2* s0 = Hc + t4 * H2_SLICE + hoff;
        const __half2* s1 = Hc + (t4 + 4) * H2_SLICE + hoff;
        #pragma unroll
        for (int nf = 0; nf < 8; nf++) {
            b[nf][0] = *(const unsigned*)(s0 + ib2[nf]);
            b[nf][1] = *(const unsigned*)(s1 + ib2[nf]);
        }
    };

    float acc[4][8][4] = {};
    unsigned aA[4][4], bA[8][2], aB[4][4], bB[8][2];

    loadT(0); loadT(1); loadT(2); loadT(3);   // stage0 group includes H(0)
    cpwait2();
    __syncthreads();                           // pads + stages 0,1 visible
    ldfr(0, aA, bA);

    for (int u = 0; u < 36; u++) {
        const int t0 = 2 * u;
        ldfr(t0 + 1, aB, bB);
        #pragma unroll
        for (int mf = 0; mf < 4; mf++)
            #pragma unroll
            for (int nf = 0; nf < 8; nf++) mma16(acc[mf][nf], aA[mf], bA[nf]);
        #pragma unroll
        for (int mf = 0; mf < 4; mf++)
            #pragma unroll
            for (int nf = 0; nf < 8; nf++) mma16(acc[mf][nf], aB[mf], bB[nf]);
        if (u + 1 < 36) {
            cpwait0();
            __syncthreads();
            loadT(t0 + 4); loadT(t0 + 5);
            ldfr(t0 + 2, aA, bA);
        }
    }
    cpwait0();

    __half* ob = g_rpn1h + (size_t)n * 384 * HW;
    #pragma unroll
    for (int mf = 0; mf < 4; mf++) {
        int r0 = m0 + wm + mf * 16 + g;
        float bv0 = b_c1[r0], bv1 = b_c1[r0 + 8];
        #pragma unroll
        for (int nf = 0; nf < 8; nf++) {
            int c = n0 + wn + nf * 8 + t4 * 2;
            float x0 = fmaxf(acc[mf][nf][0] + bv0, 0.f);
            float x1 = fmaxf(acc[mf][nf][1] + bv0, 0.f);
            float x2 = fmaxf(acc[mf][nf][2] + bv1, 0.f);
            float x3 = fmaxf(acc[mf][nf][3] + bv1, 0.f);
            *(__half2*)(ob + (size_t)r0 * HW + c)       = __floats2half2_rn(x0, x1);
            *(__half2*)(ob + (size_t)(r0 + 8) * HW + c) = __floats2half2_rn(x2, x3);
        }
    }
}

// ---------------------------------------------------------------------------
// Kernel 3: head. fp16 MMA + ldmatrix. N-TILE 64 (grid 512 CTAs for wave
// depth), 4 warps of 32x32, 128 thr. 24 K16 stages, one wait0+sync per pair.
// Bias + paired softmax (c, c+9) for cls, bias for box, two zero scalars.
// ---------------------------------------------------------------------------
#define HD_A_B  3072                // 64x24 halves
#define HD_B_B  2304                // 16x72 halves
#define HD_ST_B (HD_A_B + HD_B_B)   // 5376
#define HD_SMEM (4 * HD_ST_B)       // 21504 (Cs overlay 64*68*4=17408 fits)

__global__ __launch_bounds__(128)
void k_head(const float* __restrict__ b_cls, const float* __restrict__ b_box,
            float* __restrict__ out)
{
    extern __shared__ char ds[];
    const int n  = blockIdx.z;
    const int n0 = blockIdx.x * 64;
    const __half* Bp = g_rpn1h + (size_t)n * 384 * HW + n0;

    const int tid  = threadIdx.x;
    const int warp = tid >> 5, lane = tid & 31;
    const int wm = (warp >> 1) * 32, wn = (warp & 1) * 32;
    const int g  = lane >> 2, t4 = lane & 3;
    const int l15 = lane & 15, l16 = lane >> 4;

    auto loadT = [&](int s) {
        if (s < 24) {
            char* As = ds + (s & 3) * HD_ST_B;
            char* Bs = As + HD_A_B;
            const int k0 = s * 16;
            {
                int row = tid >> 1, sub = tid & 1;  // A: 128 chunks
                cp16(sptr(As + row * 48 + sub * 16),
                     g_whh + (size_t)row * 384 + k0 + sub * 8, true);
            }
            {
                int row = tid >> 3, xu = tid & 7;   // B: 16 rows x 64 halves
                cp16(sptr(Bs + row * 144 + xu * 16),
                     Bp + (size_t)(k0 + row) * HW + xu * 8, true);
            }
        }
        cpcommit();
    };

    auto ldmAB = [&](int s, unsigned (&a)[2][4], unsigned (&b)[4][2]) {
        const char* As = ds + (s & 3) * HD_ST_B;
        const char* Bs = As + HD_A_B;
        #pragma unroll
        for (int mf = 0; mf < 2; mf++) {
            unsigned addr = sptr(As) + (wm + mf * 16 + l15) * 48 + l16 * 16;
            ldm4(addr, a[mf][0], a[mf][1], a[mf][2], a[mf][3]);
        }
        #pragma unroll
        for (int p = 0; p < 2; p++) {
            unsigned addr = sptr(Bs) + l15 * 144 + (wn + p * 16 + l16 * 8) * 2;
            ldm4t(addr, b[2*p][0], b[2*p][1], b[2*p+1][0], b[2*p+1][1]);
        }
    };

    float acc[2][4][4] = {};
    unsigned aA[2][4], bA[4][2], aB[2][4], bB[4][2];

    loadT(0); loadT(1); loadT(2); loadT(3);
    cpwait2();
    __syncthreads();
    ldmAB(0, aA, bA);

    for (int u = 0; u < 12; u++) {
        const int t0 = 2 * u;
        ldmAB(t0 + 1, aB, bB);
        #pragma unroll
        for (int mf = 0; mf < 2; mf++)
            #pragma unroll
            for (int nf = 0; nf < 4; nf++) mma16(acc[mf][nf], aA[mf], bA[nf]);
        #pragma unroll
        for (int mf = 0; mf < 2; mf++)
            #pragma unroll
            for (int nf = 0; nf < 4; nf++) mma16(acc[mf][nf], aB[mf], bB[nf]);
        if (u + 1 < 12) {
            cpwait0();
            __syncthreads();
            loadT(t0 + 4); loadT(t0 + 5);
            ldmAB(t0 + 2, aA, bA);
        }
    }
    cpwait0();

    __syncthreads();                      // all warps done reading ring
    float (*Cs)[68] = (float(*)[68])ds;   // overlay
    #pragma unroll
    for (int mf = 0; mf < 2; mf++) {
        int r0 = wm + mf * 16 + g;
        #pragma unroll
        for (int nf = 0; nf < 4; nf++) {
            int c = wn + nf * 8 + t4 * 2;
            Cs[r0][c]         = acc[mf][nf][0];
            Cs[r0][c + 1]     = acc[mf][nf][1];
            Cs[r0 + 8][c]     = acc[mf][nf][2];
            Cs[r0 + 8][c + 1] = acc[mf][nf][3];
        }
    }
    __syncthreads();

    const size_t F1 = (size_t)CB * CIN * HW;
    const size_t F2 = F1 + (size_t)CB * 18 * HW;
    const size_t F3 = F2 + (size_t)CB * 36 * HW;

    for (int it = tid; it < 9 * 64; it += 128) {
        int c = it >> 6, j = it & 63;
        float s0 = Cs[c][j]     + b_cls[c];
        float s1 = Cs[c + 9][j] + b_cls[c + 9];
        float m  = fmaxf(s0, s1);
        float e0 = expf(s0 - m), e1 = expf(s1 - m);
        float inv = 1.f / (e0 + e1);
        out[F1 + (size_t)n * 18 * HW + (size_t)c * HW + n0 + j]       = e0 * inv;
        out[F1 + (size_t)n * 18 * HW + (size_t)(c + 9) * HW + n0 + j] = e1 * inv;
    }
    for (int it = tid; it < 36 * 64; it += 128) {
        int c = it >> 6, j = it & 63;
        out[F2 + (size_t)n * 36 * HW + (size_t)c * HW + n0 + j] = Cs[18 + c][j] + b_box[c];
    }
    if (n == 0 && blockIdx.x == 0 && tid == 0) {
        out[F3]     = 0.f;
        out[F3 + 1] = 0.f;
    }
}

// ---------------------------------------------------------------------------
extern "C" void kernel_launch(void* const* d_in, const int* in_sizes, int n_in,
                              void* d_out, int out_size)
{
    const float* base  = (const float*)d_in[0];
    const float* w_f   = (const float*)d_in[3];
    const float* b_f   = (const float*)d_in[4];
    const float* w_2   = (const float*)d_in[5];
    const float* b_2   = (const float*)d_in[6];
    const float* w_c1  = (const float*)d_in[7];
    const float* b_c1  = (const float*)d_in[8];
    const float* w_cls = (const float*)d_in[9];
    const float* b_cls = (const float*)d_in[10];
    const float* w_box = (const float*)d_in[11];
    const float* b_box = (const float*)d_in[12];
    float* out = (float*)d_out;

    static bool attr_set = false;
    if (!attr_set) {
        cudaFuncSetAttribute(k_conv1, cudaFuncAttributeMaxDynamicSharedMemorySize, C1_SMEM);
        cudaFuncSetAttribute(k_conv3, cudaFuncAttributeMaxDynamicSharedMemorySize, C3_SMEM);
        cudaFuncSetAttribute(k_head,  cudaFuncAttributeMaxDynamicSharedMemorySize, HD_SMEM);
        attr_set = true;
    }

    k_prep <<<(PREP_TOT + 255) / 256, 256>>>(base, w_f, w_2, w_c1, w_cls, w_box);
    k_conv1<<<dim3(32, 4, CB), 128, C1_SMEM>>>(b_f, b_2, out);
    k_conv3<<<dim3(32, 3, CB), 128, C3_SMEM>>>(b_c1);
    k_head <<<dim3(64, 1, CB), 128, HD_SMEM>>>(b_cls, b_box, out);
}

// round 15
// speedup vs baseline: 1.1000x; 1.1000x over previous
#include <cuda_runtime.h>
#include <cuda_fp16.h>
#include <cstdint>

// Problem constants
#define CB   8
#define HW   4096          // 64*64
#define CIN  512

// Device scratch (fp16: same 11-bit significand as tf32)
static __device__ __half  g_bfh[(size_t)CB * 512 * HW];   // base_feat fp16 (32MB)
static __device__ __half  g_rpn1h[(size_t)CB * 384 * HW]; // conv3 out (24MB)
static __device__ __half2 g_feath2[(size_t)CB * 64 * HW]; // convf_rpn pair-interleaved (8MB)
static __device__ __half  g_wah[512 * 512];               // [w_f; w_2]
static __device__ __half  g_wth[9 * 384 * 128];           // w_c1 tap-major
static __device__ __half  g_whh[64 * 384];                // [w_cls; w_box; 0]

// ---------------------------------------------------------------------------
// helpers
// ---------------------------------------------------------------------------
__device__ __forceinline__ void mma16(float d[4], const unsigned a[4], const unsigned b[2]) {
    asm volatile(
        "mma.sync.aligned.m16n8k16.row.col.f32.f16.f16.f32 "
        "{%0,%1,%2,%3}, {%4,%5,%6,%7}, {%8,%9}, {%0,%1,%2,%3};\n"
        : "+f"(d[0]), "+f"(d[1]), "+f"(d[2]), "+f"(d[3])
        : "r"(a[0]), "r"(a[1]), "r"(a[2]), "r"(a[3]), "r"(b[0]), "r"(b[1]));
}

__device__ __forceinline__ unsigned sptr(const void* p) {
    return (unsigned)__cvta_generic_to_shared(p);
}
__device__ __forceinline__ void cp16(unsigned d, const void* s, bool ok) {
    asm volatile("cp.async.cg.shared.global [%0], [%1], 16, %2;\n"
                 :: "r"(d), "l"(s), "r"(ok ? 16 : 0));
}
__device__ __forceinline__ void cpcommit() { asm volatile("cp.async.commit_group;\n"); }
__device__ __forceinline__ void cpwait2()  { asm volatile("cp.async.wait_group 2;\n"); }
__device__ __forceinline__ void cpwait1()  { asm volatile("cp.async.wait_group 1;\n"); }

__device__ __forceinline__ void ldm4(unsigned addr, unsigned& r0, unsigned& r1,
                                     unsigned& r2, unsigned& r3) {
    asm volatile("ldmatrix.sync.aligned.m8n8.x4.shared.b16 {%0,%1,%2,%3}, [%4];"
                 : "=r"(r0), "=r"(r1), "=r"(r2), "=r"(r3) : "r"(addr));
}
__device__ __forceinline__ void ldm4t(unsigned addr, unsigned& r0, unsigned& r1,
                                      unsigned& r2, unsigned& r3) {
    asm volatile("ldmatrix.sync.aligned.m8n8.x4.trans.shared.b16 {%0,%1,%2,%3}, [%4];"
                 : "=r"(r0), "=r"(r1), "=r"(r2), "=r"(r3) : "r"(addr));
}

// ---------------------------------------------------------------------------
// Prep: base_feat -> fp16; weights -> fp16 (tap-major for w_c1; packed head).
// ---------------------------------------------------------------------------
#define PREP_N4 4194304             // (8*512*4096)/4, float4 granularity
#define PREP_N1 262144              // 512*512
#define PREP_N2 442368              // 9*384*128
#define PREP_N3 24576               // 64*384
#define PREP_TOT (PREP_N4 + PREP_N1 + PREP_N2 + PREP_N3)

__global__ void k_prep(const float* __restrict__ base_feat,
                       const float* __restrict__ w_f, const float* __restrict__ w_2,
                       const float* __restrict__ w_c1,
                       const float* __restrict__ w_cls, const float* __restrict__ w_box)
{
    int i = blockIdx.x * 256 + threadIdx.x;
    if (i < PREP_N4) {
        float4 v = ((const float4*)base_feat)[i];
        __half2* dst = (__half2*)(g_bfh + (size_t)i * 4);
        dst[0] = __floats2half2_rn(v.x, v.y);
        dst[1] = __floats2half2_rn(v.z, v.w);
        return;
    }
    i -= PREP_N4;
    if (i < PREP_N1) {
        int m = i >> 9;
        float v = (m < 128) ? w_f[i] : w_2[i - 65536];
        g_wah[i] = __float2half_rn(v);
        return;
    }
    i -= PREP_N1;
    if (i < PREP_N2) {
        int tap = i / 49152, rem = i % 49152;
        int m = rem >> 7, c = rem & 127;
        g_wth[i] = __float2half_rn(w_c1[(size_t)m * 1152 + c * 9 + tap]);
        return;
    }
    i -= PREP_N2;
    if (i < PREP_N3) {
        int r = i / 384, k = i - r * 384;
        float v;
        if (r < 18)      v = w_cls[i];
        else if (r < 54) v = w_box[(r - 18) * 384 + k];
        else             v = 0.f;
        g_whh[i] = __float2half_rn(v);
    }
}

// ---------------------------------------------------------------------------
// Kernel 1: fused 1x1 conv 512 -> 512, ReLU -> d_out feat region.
// fp16 m16n8k16 + ldmatrix. 4 warps of 64x64, 128 thr. 8-slot K16 ring,
// ONE commit group per K32 PAIR, ONE wait_group(1)+sync per pair (keeps one
// group in flight -> load slack preserved, unlike R14's wait0).
// Invariant at top of pair u: groups <= u+1 complete -> cross-pair s0
// prefetch is safe. mt==0 also writes pair-interleaved fp16 to g_feath2.
// ---------------------------------------------------------------------------
#define C1_A_B  6144
#define C1_B_B  4352
#define C1_ST_B (C1_A_B + C1_B_B)   // 10496
#define C1_SMEM (8 * C1_ST_B)       // 83968

__global__ __launch_bounds__(128, 2)
void k_conv1(const float* __restrict__ b_f, const float* __restrict__ b_2,
             float* __restrict__ out)
{
    extern __shared__ char ds[];
    const int n  = blockIdx.z;
    const int mt = blockIdx.y;
    const int n0 = blockIdx.x * 128;
    const int mtb = mt * 128;
    const float* bi = (mt == 0) ? b_f : (b_2 + (mt - 1) * 128);
    const __half* Bp = g_bfh + (size_t)n * CIN * HW + n0;

    const int tid  = threadIdx.x;
    const int warp = tid >> 5, lane = tid & 31;
    const int wm = (warp >> 1) * 64, wn = (warp & 1) * 64;
    const int g  = lane >> 2, t4 = lane & 3;
    const int l15 = lane & 15, l16 = lane >> 4;

    auto loadS = [&](int s) {                   // one K16 stage, no commit
        if (s < 32) {
            char* As = ds + (s & 7) * C1_ST_B;
            char* Bs = As + C1_A_B;
            const int k0 = s * 16;
            #pragma unroll
            for (int j = 0; j < 2; j++) {
                int e = tid + j * 128;
                int row = e >> 1, sub = e & 1;
                cp16(sptr(As + row * 48 + sub * 16),
                     g_wah + (size_t)(mtb + row) * 512 + k0 + sub * 8, true);
                int brow = e >> 4, xu = e & 15;
                cp16(sptr(Bs + brow * 272 + xu * 16),
                     Bp + (size_t)(k0 + brow) * HW + xu * 8, true);
            }
        }
    };
    auto loadPair = [&](int p) {                // one commit per pair
        loadS(2 * p); loadS(2 * p + 1);
        cpcommit();
    };

    auto ldmAB = [&](int s, unsigned (&a)[4][4], unsigned (&b)[8][2]) {
        const char* As = ds + (s & 7) * C1_ST_B;
        const char* Bs = As + C1_A_B;
        #pragma unroll
        for (int mf = 0; mf < 4; mf++) {
            unsigned addr = sptr(As) + (wm + mf * 16 + l15) * 48 + l16 * 16;
            ldm4(addr, a[mf][0], a[mf][1], a[mf][2], a[mf][3]);
        }
        #pragma unroll
        for (int p = 0; p < 4; p++) {
            unsigned addr = sptr(Bs) + l15 * 272 + (wn + p * 16 + l16 * 8) * 2;
            ldm4t(addr, b[2*p][0], b[2*p][1], b[2*p+1][0], b[2*p+1][1]);
        }
    };

    float acc[4][8][4] = {};
    unsigned aA[4][4], bA[8][2], aB[4][4], bB[8][2];

    loadPair(0); loadPair(1); loadPair(2);
    cpwait2();                                  // G0 complete
    __syncthreads();
    ldmAB(0, aA, bA);

    for (int u = 0; u < 16; u++) {
        cpwait1();                              // groups <= u+1 complete
        __syncthreads();
        loadPair(u + 3);                        // commits (maybe empty)

        ldmAB(2 * u + 1, aB, bB);
        #pragma unroll
        for (int mf = 0; mf < 4; mf++)
            #pragma unroll
            for (int nf = 0; nf < 8; nf++) mma16(acc[mf][nf], aA[mf], bA[nf]);
        if (u + 1 < 16) ldmAB(2 * u + 2, aA, bA);
        #pragma unroll
        for (int mf = 0; mf < 4; mf++)
            #pragma unroll
            for (int nf = 0; nf < 8; nf++) mma16(acc[mf][nf], aB[mf], bB[nf]);
    }

    float*   outb = out + (size_t)n * CIN * HW + (size_t)mt * 128 * HW;
    __half2* gf2  = g_feath2 + (size_t)n * 64 * HW;
    #pragma unroll
    for (int mf = 0; mf < 4; mf++) {
        int r0 = wm + mf * 16 + g;
        float bv0 = bi[r0], bv1 = bi[r0 + 8];
        #pragma unroll
        for (int nf = 0; nf < 8; nf++) {
            int c = n0 + wn + nf * 8 + t4 * 2;
            float2 v0, v1;
            v0.x = fmaxf(acc[mf][nf][0] + bv0, 0.f);
            v0.y = fmaxf(acc[mf][nf][1] + bv0, 0.f);
            v1.x = fmaxf(acc[mf][nf][2] + bv1, 0.f);
            v1.y = fmaxf(acc[mf][nf][3] + bv1, 0.f);
            *(float2*)(outb + (size_t)r0 * HW + c)       = v0;
            *(float2*)(outb + (size_t)(r0 + 8) * HW + c) = v1;
            if (mt == 0) {
                // pair-interleave: partner lane+4 holds channel r0+1
                float p0x = __shfl_down_sync(0xffffffffu, v0.x, 4);
                float p0y = __shfl_down_sync(0xffffffffu, v0.y, 4);
                float p1x = __shfl_down_sync(0xffffffffu, v1.x, 4);
                float p1y = __shfl_down_sync(0xffffffffu, v1.y, 4);
                if (!(g & 1)) {
                    __half2* d0 = gf2 + (size_t)(r0 >> 1) * HW + c;
                    d0[0] = __floats2half2_rn(v0.x, p0x);
                    d0[1] = __floats2half2_rn(v0.y, p0y);
                    __half2* d1 = gf2 + (size_t)((r0 >> 1) + 4) * HW + c;
                    d1[0] = __floats2half2_rn(v1.x, p1x);
                    d1[1] = __floats2half2_rn(v1.y, p1y);
                }
            }
        }
    }
}

// ---------------------------------------------------------------------------
// Kernel 2: 3x3 conv 128 -> 384 pad=1, ReLU -> g_rpn1h (fp16).
// fp16 m16n8k16. A via ldmatrix from 8-slot K16 ring, one commit+wait1+sync
// per K32 pair. B = one aligned LDS.32 per register from pair-interleaved
// halo tiles. H(kc) bundled into the pair group containing stage 9kc
// (write begins >= 4 pairs after buffer's last read; completion covered by
// the pair invariant). 2 H buffers at kc cadence.
// ---------------------------------------------------------------------------
#define H2_ROW   68
#define H2_PAD   4
#define H2_SLICE 280                // __half2 units
#define H2_BUF   (8 * H2_SLICE)     // 2240 __half2 per buffer
#define C3_A_B   6144
#define C3_SMEM  (8 * C3_A_B + 2 * H2_BUF * 4)   // 49152 + 17920 = 67072

__global__ __launch_bounds__(128, 2)
void k_conv3(const float* __restrict__ b_c1)
{
    extern __shared__ char ds[];
    __half2* Hb2 = (__half2*)(ds + 8 * C3_A_B);

    const int n  = blockIdx.z;
    const int m0 = blockIdx.y * 128;
    const int n0 = blockIdx.x * 128;
    const int y0 = blockIdx.x * 2;

    const int tid  = threadIdx.x;
    const int warp = tid >> 5, lane = tid & 31;
    const int wm = (warp >> 1) * 64, wn = (warp & 1) * 64;
    const int g  = lane >> 2, t4 = lane & 3;
    const int l15 = lane & 15, l16 = lane >> 4;

    // zero pads: per (buf,k2): front 4 __half2 + halo cols 64..67 of 4 rows
    for (int i = tid; i < 320; i += 128) {
        int buf = i / 160, r2 = i % 160;
        int k2 = r2 / 20, e = r2 % 20;
        int off = (e < 4) ? e
                          : H2_PAD + ((e - 4) >> 2) * H2_ROW + 64 + ((e - 4) & 3);
        Hb2[buf * H2_BUF + k2 * H2_SLICE + off] = __floats2half2_rn(0.f, 0.f);
    }

    auto loadH = [&](int kc, int buf) {
        const __half2* src = g_feath2 + (size_t)n * 64 * HW;
        #pragma unroll
        for (int j = 0; j < 4; j++) {
            int e = tid + j * 128;                 // 0..511
            int k2 = e >> 6, rem = e & 63, r = rem >> 4, xu = rem & 15;
            int gy = y0 - 1 + r;
            cp16(sptr(Hb2 + buf * H2_BUF + k2 * H2_SLICE + H2_PAD + r * H2_ROW + xu * 4),
                 src + (size_t)(kc * 8 + k2) * HW + gy * 64 + xu * 4,
                 (unsigned)gy < 64u);
        }
    };
    auto loadS = [&](int s) {                     // one K16 stage, no commit
        if (s < 72) {
            int kc = s / 9, tap = s - kc * 9;
            char* As = ds + (s & 7) * C3_A_B;
            #pragma unroll
            for (int j = 0; j < 2; j++) {
                int e = tid + j * 128;
                int row = e >> 1, sub = e & 1;
                cp16(sptr(As + row * 48 + sub * 16),
                     g_wth + ((size_t)tap * 384 + m0 + row) * 128 + kc * 16 + sub * 8, true);
            }
            if (tap == 0 && kc < 8) loadH(kc, kc & 1);
        }
    };
    auto loadPair = [&](int p) {
        loadS(2 * p); loadS(2 * p + 1);
        cpcommit();
    };

    int ib2[8];
    #pragma unroll
    for (int nf = 0; nf < 8; nf++) {
        int px = wn + nf * 8 + g;
        ib2[nf] = H2_PAD + (1 + (px >> 6)) * H2_ROW + (px & 63);
    }

    auto ldfr = [&](int s, unsigned (&a)[4][4], unsigned (&b)[8][2]) {
        int kc = s / 9, tap = s - kc * 9;
        int hoff = (tap / 3 - 1) * H2_ROW + (tap % 3 - 1);
        const char* As = ds + (s & 7) * C3_A_B;
        const __half2* Hc = Hb2 + (kc & 1) * H2_BUF;
        #pragma unroll
        for (int mf = 0; mf < 4; mf++) {
            unsigned addr = sptr(As) + (wm + mf * 16 + l15) * 48 + l16 * 16;
            ldm4(addr, a[mf][0], a[mf][1], a[mf][2], a[mf][3]);
        }
        const __half2* s0 = Hc + t4 * H2_SLICE + hoff;
        const __half2* s1 = Hc + (t4 + 4) * H2_SLICE + hoff;
        #pragma unroll
        for (int nf = 0; nf < 8; nf++) {
            b[nf][0] = *(const unsigned*)(s0 + ib2[nf]);
            b[nf][1] = *(const unsigned*)(s1 + ib2[nf]);
        }
    };

    float acc[4][8][4] = {};
    unsigned aA[4][4], bA[8][2], aB[4][4], bB[8][2];

    loadPair(0); loadPair(1); loadPair(2);    // G0 includes H(0)
    cpwait2();                                 // G0 complete
    __syncthreads();                           // pads + G0 visible
    ldfr(0, aA, bA);

    for (int u = 0; u < 36; u++) {
        cpwait1();                             // groups <= u+1 complete
        __syncthreads();
        loadPair(u + 3);

        ldfr(2 * u + 1, aB, bB);
        #pragma unroll
        for (int mf = 0; mf < 4; mf++)
            #pragma unroll
            for (int nf = 0; nf < 8; nf++) mma16(acc[mf][nf], aA[mf], bA[nf]);
        if (u + 1 < 36) ldfr(2 * u + 2, aA, bA);
        #pragma unroll
        for (int mf = 0; mf < 4; mf++)
            #pragma unroll
            for (int nf = 0; nf < 8; nf++) mma16(acc[mf][nf], aB[mf], bB[nf]);
    }

    __half* ob = g_rpn1h + (size_t)n * 384 * HW;
    #pragma unroll
    for (int mf = 0; mf < 4; mf++) {
        int r0 = m0 + wm + mf * 16 + g;
        float bv0 = b_c1[r0], bv1 = b_c1[r0 + 8];
        #pragma unroll
        for (int nf = 0; nf < 8; nf++) {
            int c = n0 + wn + nf * 8 + t4 * 2;
            float x0 = fmaxf(acc[mf][nf][0] + bv0, 0.f);
            float x1 = fmaxf(acc[mf][nf][1] + bv0, 0.f);
            float x2 = fmaxf(acc[mf][nf][2] + bv1, 0.f);
            float x3 = fmaxf(acc[mf][nf][3] + bv1, 0.f);
            *(__half2*)(ob + (size_t)r0 * HW + c)       = __floats2half2_rn(x0, x1);
            *(__half2*)(ob + (size_t)(r0 + 8) * HW + c) = __floats2half2_rn(x2, x3);
        }
    }
}

// ---------------------------------------------------------------------------
// Kernel 3: head (R13 version, known-good). fp16 MMA + full ldmatrix.
// 4 warps of 32x64, 128 thr, N-tile 128. 24 K16 stages, 4-stage ring,
// per-stage wait1+sync. Bias + paired softmax (c, c+9) for cls, bias for
// box, two zero scalars. Cs overlay needs 33792B.
// ---------------------------------------------------------------------------
#define HD_A_B  3072
#define HD_B_B  4352
#define HD_ST_B (HD_A_B + HD_B_B)   // 7424
#define HD_SMEM 34048               // max(4*7424=29696, Cs 33792) + pad

__global__ __launch_bounds__(128)
void k_head(const float* __restrict__ b_cls, const float* __restrict__ b_box,
            float* __restrict__ out)
{
    extern __shared__ char ds[];
    const int n  = blockIdx.z;
    const int n0 = blockIdx.x * 128;
    const __half* Bp = g_rpn1h + (size_t)n * 384 * HW + n0;

    const int tid  = threadIdx.x;
    const int warp = tid >> 5, lane = tid & 31;
    const int wm = (warp >> 1) * 32, wn = (warp & 1) * 64;
    const int g  = lane >> 2, t4 = lane & 3;
    const int l15 = lane & 15, l16 = lane >> 4;

    auto loadT = [&](int s) {
        if (s < 24) {
            char* As = ds + (s & 3) * HD_ST_B;
            char* Bs = As + HD_A_B;
            const int k0 = s * 16;
            {
                int row = tid >> 1, sub = tid & 1;  // 128 chunks
                cp16(sptr(As + row * 48 + sub * 16),
                     g_whh + (size_t)row * 384 + k0 + sub * 8, true);
            }
            #pragma unroll
            for (int j = 0; j < 2; j++) {
                int e = tid + j * 128;
                int row = e >> 4, xu = e & 15;
                cp16(sptr(Bs + row * 272 + xu * 16),
                     Bp + (size_t)(k0 + row) * HW + xu * 8, true);
            }
        }
        cpcommit();
    };

    auto ldmAB = [&](int s, unsigned (&a)[2][4], unsigned (&b)[8][2]) {
        const char* As = ds + (s & 3) * HD_ST_B;
        const char* Bs = As + HD_A_B;
        #pragma unroll
        for (int mf = 0; mf < 2; mf++) {
            unsigned addr = sptr(As) + (wm + mf * 16 + l15) * 48 + l16 * 16;
            ldm4(addr, a[mf][0], a[mf][1], a[mf][2], a[mf][3]);
        }
        #pragma unroll
        for (int p = 0; p < 4; p++) {
            unsigned addr = sptr(Bs) + l15 * 272 + (wn + p * 16 + l16 * 8) * 2;
            ldm4t(addr, b[2*p][0], b[2*p][1], b[2*p+1][0], b[2*p+1][1]);
        }
    };

    float acc[2][8][4] = {};
    unsigned aA[2][4], bA[8][2], aB[2][4], bB[8][2];

    loadT(0); loadT(1); loadT(2);
    cpwait1();
    __syncthreads();
    ldmAB(0, aA, bA);

    for (int u = 0; u < 12; u++) {
        const int t0 = 2 * u;
        if (t0) { cpwait1(); __syncthreads(); }
        loadT(t0 + 3);
        ldmAB(t0 + 1, aB, bB);
        #pragma unroll
        for (int mf = 0; mf < 2; mf++)
            #pragma unroll
            for (int nf = 0; nf < 8; nf++) mma16(acc[mf][nf], aA[mf], bA[nf]);

        cpwait1(); __syncthreads();
        loadT(t0 + 4);
        if (t0 + 2 < 24) ldmAB(t0 + 2, aA, bA);
        #pragma unroll
        for (int mf = 0; mf < 2; mf++)
            #pragma unroll
            for (int nf = 0; nf < 8; nf++) mma16(acc[mf][nf], aB[mf], bB[nf]);
    }

    __syncthreads();                       // all warps done reading ring
    float (*Cs)[132] = (float(*)[132])ds;  // overlay
    #pragma unroll
    for (int mf = 0; mf < 2; mf++) {
        int r0 = wm + mf * 16 + g;
        #pragma unroll
        for (int nf = 0; nf < 8; nf++) {
            int c = wn + nf * 8 + t4 * 2;
            Cs[r0][c]         = acc[mf][nf][0];
            Cs[r0][c + 1]     = acc[mf][nf][1];
            Cs[r0 + 8][c]     = acc[mf][nf][2];
            Cs[r0 + 8][c + 1] = acc[mf][nf][3];
        }
    }
    __syncthreads();

    const size_t F1 = (size_t)CB * CIN * HW;
    const size_t F2 = F1 + (size_t)CB * 18 * HW;
    const size_t F3 = F2 + (size_t)CB * 36 * HW;

    for (int it = tid; it < 9 * 128; it += 128) {
        int c = it >> 7, j = it & 127;
        float s0 = Cs[c][j]     + b_cls[c];
        float s1 = Cs[c + 9][j] + b_cls[c + 9];
        float m  = fmaxf(s0, s1);
        float e0 = expf(s0 - m), e1 = expf(s1 - m);
        float inv = 1.f / (e0 + e1);
        out[F1 + (size_t)n * 18 * HW + (size_t)c * HW + n0 + j]       = e0 * inv;
        out[F1 + (size_t)n * 18 * HW + (size_t)(c + 9) * HW + n0 + j] = e1 * inv;
    }
    for (int it = tid; it < 36 * 128; it += 128) {
        int c = it >> 7, j = it & 127;
        out[F2 + (size_t)n * 36 * HW + (size_t)c * HW + n0 + j] = Cs[18 + c][j] + b_box[c];
    }
    if (n == 0 && blockIdx.x == 0 && tid == 0) {
        out[F3]     = 0.f;
        out[F3 + 1] = 0.f;
    }
}

// ---------------------------------------------------------------------------
extern "C" void kernel_launch(void* const* d_in, const int* in_sizes, int n_in,
                              void* d_out, int out_size)
{
    const float* base  = (const float*)d_in[0];
    const float* w_f   = (const float*)d_in[3];
    const float* b_f   = (const float*)d_in[4];
    const float* w_2   = (const float*)d_in[5];
    const float* b_2   = (const float*)d_in[6];
    const float* w_c1  = (const float*)d_in[7];
    const float* b_c1  = (const float*)d_in[8];
    const float* w_cls = (const float*)d_in[9];
    const float* b_cls = (const float*)d_in[10];
    const float* w_box = (const float*)d_in[11];
    const float* b_box = (const float*)d_in[12];
    float* out = (float*)d_out;

    static bool attr_set = false;
    if (!attr_set) {
        cudaFuncSetAttribute(k_conv1, cudaFuncAttributeMaxDynamicSharedMemorySize, C1_SMEM);
        cudaFuncSetAttribute(k_conv3, cudaFuncAttributeMaxDynamicSharedMemorySize, C3_SMEM);
        cudaFuncSetAttribute(k_head,  cudaFuncAttributeMaxDynamicSharedMemorySize, HD_SMEM);
        attr_set = true;
    }

    k_prep <<<(PREP_TOT + 255) / 256, 256>>>(base, w_f, w_2, w_c1, w_cls, w_box);
    k_conv1<<<dim3(32, 4, CB), 128, C1_SMEM>>>(b_f, b_2, out);
    k_conv3<<<dim3(32, 3, CB), 128, C3_SMEM>>>(b_c1);
    k_head <<<dim3(32, 1, CB), 128, HD_SMEM>>>(b_cls, b_box, out);
}